// round 6
// baseline (speedup 1.0000x reference)
#include <cuda_runtime.h>
#include <cstdint>

#define NGRAPH 4096
#define EPS 1e-6f

// ---------------- device scratch (no allocations allowed) ----------------
__device__ __align__(16) float g_att[262144 * 8];          // exp attention, unnormalized [N,8]
__device__ __align__(16) float g_outflat[NGRAPH * 1024];   // aggregated [B, H*D]
__device__ __align__(16) float g_W3h[1024 * 128];
__device__ __align__(16) float g_W3l[1024 * 128];
__device__ __align__(16) float g_W4h[128 * 128];
__device__ __align__(16) float g_W4l[128 * 128];
__device__ int g_is64;                                     // batch dtype flag

__device__ __forceinline__ float leaky(float x){ return x > 0.f ? x : 0.01f * x; }

// tf32 round-to-nearest (result in f32 register with low mantissa bits zero)
__device__ __forceinline__ float tf32_rn(float x){
    uint32_t u;
    asm("cvt.rna.tf32.f32 %0, %1;" : "=r"(u) : "f"(x));
    return __uint_as_float(u);
}

// D += A(16x8 tf32) * B(8x8 tf32), fp32 accumulate
__device__ __forceinline__ void mma_tf32(float* c,
    float a0, float a1, float a2, float a3, float b0, float b1){
    asm volatile(
      "mma.sync.aligned.m16n8k8.row.col.f32.tf32.tf32.f32 "
      "{%0,%1,%2,%3}, {%4,%5,%6,%7}, {%8,%9}, {%0,%1,%2,%3};\n"
      : "+f"(c[0]), "+f"(c[1]), "+f"(c[2]), "+f"(c[3])
      : "r"(__float_as_uint(a0)), "r"(__float_as_uint(a1)),
        "r"(__float_as_uint(a2)), "r"(__float_as_uint(a3)),
        "r"(__float_as_uint(b0)), "r"(__float_as_uint(b1)));
}

// batch dtype detection with int32 loads only
__global__ void detect_kernel(const int* __restrict__ batch, int n){
    int base = n / 2;
    int ok64 = 1;
    for (int i = 0; i < 256; i++){
        int lo = batch[base + 2*i];
        int hi = batch[base + 2*i + 1];
        if (hi != 0 || lo < 0 || lo >= NGRAPH){ ok64 = 0; break; }
    }
    g_is64 = ok64;
}

__device__ __forceinline__ int bat(const int* b, int i, int is64){
    return is64 ? b[2*i] : b[i];
}

__device__ __forceinline__ int lbound(const int* b, int n, int val, int is64){
    int lo = 0, hi = n;
    while (lo < hi){
        int mid = (lo + hi) >> 1;
        if (bat(b, mid, is64) < val) lo = mid + 1; else hi = mid;
    }
    return lo;
}

// ---------------- weight prep: one-time tf32 hi/lo split of W3, W4 ----------------
__global__ void prep_kernel(const float* __restrict__ W3, const float* __restrict__ W4){
    int i = blockIdx.x * 256 + threadIdx.x;
    if (i < 1024*128){
        float w = W3[i];
        float h = tf32_rn(w);
        g_W3h[i] = h; g_W3l[i] = tf32_rn(w - h);
    }
    int j = i - 1024*128;
    if (j >= 0 && j < 128*128){
        float w = W4[j];
        float h = tf32_rn(w);
        g_W4h[j] = h; g_W4l[j] = tf32_rn(w - h);
    }
}

// ---------------- Pass A: fused GEMM1(tf32 mma) + leaky + LN + GEMM2 + exp ----------------
// 64 rows / block, 128 threads (4 warps, each 2 m-tiles x 4 n-tiles), 4096 blocks.
// Strides: sA 132 (bank = 4g+t4, conflict-free), sW1h/l 72 (bank = 8t4+g, conflict-free).
#define ATT_SMEM_FLOATS (8448 + 9216 + 9216 + 512 + 64*3 + 8 + 128)

__global__ __launch_bounds__(128) void att_kernel(
    const float* __restrict__ feat,
    const float* __restrict__ W1, const float* __restrict__ b1,
    const float* __restrict__ g1, const float* __restrict__ be1,
    const float* __restrict__ W2, const float* __restrict__ b2)
{
    extern __shared__ float sm[];
    float* sA   = sm;              // 64 x 132 = 8448
    float* sW1h = sA + 8448;       // 128 x 72 = 9216
    float* sW1l = sW1h + 9216;     // 9216
    float* sW2  = sW1l + 9216;     // 512
    float* sB1  = sW2 + 512;       // 64
    float* sG1  = sB1 + 64;        // 64
    float* sBe1 = sG1 + 64;        // 64
    float* sB2  = sBe1 + 64;       // 8
    float* sMu  = sB2 + 8;         // 64
    float* sIs  = sMu + 64;        // 64
    float* sH   = sA;              // alias, stride 65 (4160 <= 8448)

    int t = threadIdx.x;
    int row0 = blockIdx.x * 64;
    int wid = t >> 5, lane = t & 31;
    int g = lane >> 2, t4 = lane & 3;
    int mw = wid & 1, nw = wid >> 1;

    {   // stage feat 64x128 (2048 float4, 16/thread)
        const float4* gsrc = (const float4*)(feat + (size_t)row0 * 128);
        #pragma unroll
        for (int e = 0; e < 16; e++){
            int i4 = t + 128*e;
            int r = i4 >> 5, c4 = i4 & 31;
            *(float4*)&sA[r*132 + 4*c4] = gsrc[i4];
        }
    }
    {   // stage W1 hi/lo (2048 float4 source, 16/thread)
        const float4* gsrc = (const float4*)W1;
        #pragma unroll
        for (int e = 0; e < 16; e++){
            int i4 = t + 128*e;
            int k = i4 >> 4, c4 = i4 & 15;
            float4 w = gsrc[i4];
            float4 h, l;
            h.x = tf32_rn(w.x); l.x = tf32_rn(w.x - h.x);
            h.y = tf32_rn(w.y); l.y = tf32_rn(w.y - h.y);
            h.z = tf32_rn(w.z); l.z = tf32_rn(w.z - h.z);
            h.w = tf32_rn(w.w); l.w = tf32_rn(w.w - h.w);
            *(float4*)&sW1h[k*72 + 4*c4] = h;
            *(float4*)&sW1l[k*72 + 4*c4] = l;
        }
    }
    ((float4*)sW2)[t] = ((const float4*)W2)[t];   // 128 float4 = full W2
    if (t < 64){ sB1[t] = b1[t]; sG1[t] = g1[t]; sBe1[t] = be1[t]; }
    if (t < 8)  sB2[t] = b2[t];
    __syncthreads();

    // GEMM1: warp covers rows [mw*32, mw*32+32), cols [nw*32, nw*32+32)
    float acc[2][4][4];
    #pragma unroll
    for (int mt = 0; mt < 2; mt++)
        #pragma unroll
        for (int j = 0; j < 4; j++){
            acc[mt][j][0]=0.f; acc[mt][j][1]=0.f; acc[mt][j][2]=0.f; acc[mt][j][3]=0.f;
        }

    #pragma unroll 2
    for (int ks = 0; ks < 16; ks++){
        int k0 = ks * 8;
        float ah[2][4], al[2][4];
        #pragma unroll
        for (int mt = 0; mt < 2; mt++){
            const float* R0 = sA + (mw*32 + mt*16 + g)*132 + k0;
            const float* R1 = R0 + 8*132;
            float a0 = R0[t4], a1 = R1[t4], a2 = R0[t4+4], a3 = R1[t4+4];
            ah[mt][0]=tf32_rn(a0); al[mt][0]=tf32_rn(a0-ah[mt][0]);
            ah[mt][1]=tf32_rn(a1); al[mt][1]=tf32_rn(a1-ah[mt][1]);
            ah[mt][2]=tf32_rn(a2); al[mt][2]=tf32_rn(a2-ah[mt][2]);
            ah[mt][3]=tf32_rn(a3); al[mt][3]=tf32_rn(a3-ah[mt][3]);
        }
        #pragma unroll
        for (int j = 0; j < 4; j++){
            int kr = (k0 + t4)*72 + nw*32 + j*8 + g;
            float bh0 = sW1h[kr],        bl0 = sW1l[kr];
            float bh1 = sW1h[kr + 4*72], bl1 = sW1l[kr + 4*72];
            #pragma unroll
            for (int mt = 0; mt < 2; mt++){
                mma_tf32(acc[mt][j], ah[mt][0],ah[mt][1],ah[mt][2],ah[mt][3], bh0,bh1);
                mma_tf32(acc[mt][j], al[mt][0],al[mt][1],al[mt][2],al[mt][3], bh0,bh1);
                mma_tf32(acc[mt][j], ah[mt][0],ah[mt][1],ah[mt][2],ah[mt][3], bl0,bl1);
            }
        }
    }
    __syncthreads();   // all sA reads complete before aliasing as sH

    {   // epilogue: bias + leaky -> sH (stride 65)
        #pragma unroll
        for (int mt = 0; mt < 2; mt++){
            int rA = mw*32 + mt*16 + g, rB = rA + 8;
            #pragma unroll
            for (int j = 0; j < 4; j++){
                int c = nw*32 + j*8 + 2*t4;
                sH[rA*65 + c]     = leaky(acc[mt][j][0] + sB1[c]);
                sH[rA*65 + c + 1] = leaky(acc[mt][j][1] + sB1[c+1]);
                sH[rB*65 + c]     = leaky(acc[mt][j][2] + sB1[c]);
                sH[rB*65 + c + 1] = leaky(acc[mt][j][3] + sB1[c+1]);
            }
        }
    }
    __syncthreads();

    if (t < 64){   // LN stats per row
        float sum = 0.f, ss = 0.f;
        #pragma unroll 8
        for (int j = 0; j < 64; j++){ float v = sH[t*65 + j]; sum += v; ss += v*v; }
        float mu = sum * (1.f/64.f);
        float var = ss * (1.f/64.f) - mu*mu;
        sMu[t] = mu; sIs[t] = rsqrtf(var + EPS);
    }
    __syncthreads();

    {   // GEMM2 (64->8) + exp, 2 threads per row x 4 outputs
        int row = t >> 1, half = t & 1, kb = half * 4;
        float mu = sMu[row], is = sIs[row];
        float a0=0.f, a1=0.f, a2=0.f, a3=0.f;
        #pragma unroll 4
        for (int j = 0; j < 64; j++){
            float hn = (sH[row*65 + j] - mu) * is * sG1[j] + sBe1[j];
            a0 += hn * sW2[j*8 + kb + 0];
            a1 += hn * sW2[j*8 + kb + 1];
            a2 += hn * sW2[j*8 + kb + 2];
            a3 += hn * sW2[j*8 + kb + 3];
        }
        int grow = row0 + row;
        float4 o;
        o.x = __expf(a0 + sB2[kb+0]);
        o.y = __expf(a1 + sB2[kb+1]);
        o.z = __expf(a2 + sB2[kb+2]);
        o.w = __expf(a3 + sB2[kb+3]);
        *(float4*)&g_att[grow*8 + kb] = o;
    }
}

// ---------------- Pass B: single-pass segment softmax + aggregation ----------------
__global__ __launch_bounds__(256) void aggregate_kernel(
    const float* __restrict__ feat, const int* __restrict__ batchp, int nrows)
{
    int gi = blockIdx.x;
    __shared__ int s_lo, s_hi;
    __shared__ __align__(16) float sF[32][128];
    __shared__ __align__(16) float sAtt[32][8];

    int is64 = g_is64;
    int t = threadIdx.x;
    if (t == 0)  s_lo = lbound(batchp, nrows, gi, is64);
    if (t == 32) s_hi = lbound(batchp, nrows, gi + 1, is64);
    __syncthreads();
    int lo = s_lo, hi = s_hi;
    int h = t >> 5, lane = t & 31;

    float4 acc = make_float4(0.f, 0.f, 0.f, 0.f);
    float ssum = 0.f;

    for (int base = lo; base < hi; base += 32){
        int cnt = min(32, hi - base);
        __syncthreads();
        for (int idx4 = t; idx4 < cnt*32; idx4 += 256){
            int r = idx4 >> 5, c4 = idx4 & 31;
            *(float4*)&sF[r][4*c4] = *(const float4*)&feat[(size_t)(base + r) * 128 + 4*c4];
        }
        if (t < cnt*8){
            int r = t >> 3, k = t & 7;
            sAtt[r][k] = g_att[(base + r)*8 + k];
        }
        __syncthreads();
        for (int r = 0; r < cnt; r++){
            float a = sAtt[r][h];
            ssum += a;
            float4 f = *(const float4*)&sF[r][lane*4];
            acc.x += a*f.x; acc.y += a*f.y; acc.z += a*f.z; acc.w += a*f.w;
        }
    }
    float inv = (hi > lo) ? 1.f / ssum : 0.f;
    acc.x *= inv; acc.y *= inv; acc.z *= inv; acc.w *= inv;
    *(float4*)&g_outflat[gi*1024 + h*128 + lane*4] = acc;
}

// ---------------- Pass C: GEMM3(tf32)+leaky+LN, GEMM4(tf32)+leaky+LN ----------------
// 32 graphs / block, 128 blocks, 256 threads.
// Strides: sAh/sAl 132 (A bank 4g+t4), sWh/sWl 136 (B bank 8t4+g) — conflict-free.
#define FIN_SMEM_FLOATS (4224 + 4224 + 17408 + 17408 + 128*6 + 64)

__global__ __launch_bounds__(256) void final_kernel(
    const float* __restrict__ b3,
    const float* __restrict__ g3, const float* __restrict__ be3,
    const float* __restrict__ b4,
    const float* __restrict__ g4, const float* __restrict__ be4,
    float* __restrict__ out)
{
    extern __shared__ float sm[];
    float* sAh = sm;               // 32 x 132 = 4224
    float* sAl = sAh + 4224;       // 4224
    float* sWh = sAl + 4224;       // 128 x 136 = 17408
    float* sWl = sWh + 17408;      // 17408
    float* sB3 = sWl + 17408;
    float* sG3 = sB3 + 128;
    float* sBe3= sG3 + 128;
    float* sB4 = sBe3+ 128;
    float* sG4 = sB4 + 128;
    float* sBe4= sG4 + 128;
    float* sMu = sBe4+ 128;        // 32
    float* sIs = sMu + 32;         // 32

    int t = threadIdx.x;
    int g0 = blockIdx.x * 32;
    int wid = t >> 5, lane = t & 31;
    int g = lane >> 2, t4 = lane & 3;

    if (t < 128){
        sB3[t]=b3[t]; sG3[t]=g3[t]; sBe3[t]=be3[t];
        sB4[t]=b4[t]; sG4[t]=g4[t]; sBe4[t]=be4[t];
    }

    // ---- GEMM3: [32,1024] @ [1024,128] in 8 k-tiles ----
    float acc[2][2][4];
    #pragma unroll
    for (int mt = 0; mt < 2; mt++)
        #pragma unroll
        for (int jj = 0; jj < 2; jj++){
            acc[mt][jj][0]=0.f; acc[mt][jj][1]=0.f; acc[mt][jj][2]=0.f; acc[mt][jj][3]=0.f;
        }

    for (int kt = 0; kt < 8; kt++){
        __syncthreads();
        {   // stage A slice 32x128 as hi/lo (1024 float4, 4/thread)
            #pragma unroll
            for (int e = 0; e < 4; e++){
                int i4 = t + 256*e;
                int r = i4 >> 5, c4 = i4 & 31;
                float4 a = *(const float4*)&g_outflat[(g0 + r)*1024 + kt*128 + 4*c4];
                float4 h, l;
                h.x = tf32_rn(a.x); l.x = tf32_rn(a.x - h.x);
                h.y = tf32_rn(a.y); l.y = tf32_rn(a.y - h.y);
                h.z = tf32_rn(a.z); l.z = tf32_rn(a.z - h.z);
                h.w = tf32_rn(a.w); l.w = tf32_rn(a.w - h.w);
                *(float4*)&sAh[r*132 + 4*c4] = h;
                *(float4*)&sAl[r*132 + 4*c4] = l;
            }
        }
        {   // stage W3 hi/lo k-tile (pre-split in global)
            const float4* wh = (const float4*)(g_W3h + (size_t)kt * 16384);
            const float4* wl = (const float4*)(g_W3l + (size_t)kt * 16384);
            #pragma unroll
            for (int e = 0; e < 16; e++){
                int i4 = t + 256*e;
                int k = i4 >> 5, c4 = i4 & 31;
                *(float4*)&sWh[k*136 + 4*c4] = wh[i4];
                *(float4*)&sWl[k*136 + 4*c4] = wl[i4];
            }
        }
        __syncthreads();

        #pragma unroll 2
        for (int ks = 0; ks < 16; ks++){
            int k0 = ks * 8;
            float ah[2][4], al[2][4];
            #pragma unroll
            for (int mt = 0; mt < 2; mt++){
                int ro = (mt*16 + g)*132 + k0;
                ah[mt][0]=sAh[ro+t4];       al[mt][0]=sAl[ro+t4];
                ah[mt][1]=sAh[ro+8*132+t4]; al[mt][1]=sAl[ro+8*132+t4];
                ah[mt][2]=sAh[ro+t4+4];     al[mt][2]=sAl[ro+t4+4];
                ah[mt][3]=sAh[ro+8*132+t4+4]; al[mt][3]=sAl[ro+8*132+t4+4];
            }
            #pragma unroll
            for (int jj = 0; jj < 2; jj++){
                int kr = (k0 + t4)*136 + wid*16 + jj*8 + g;
                float bh0 = sWh[kr],         bl0 = sWl[kr];
                float bh1 = sWh[kr + 4*136], bl1 = sWl[kr + 4*136];
                #pragma unroll
                for (int mt = 0; mt < 2; mt++){
                    mma_tf32(acc[mt][jj], ah[mt][0],ah[mt][1],ah[mt][2],ah[mt][3], bh0,bh1);
                    mma_tf32(acc[mt][jj], al[mt][0],al[mt][1],al[mt][2],al[mt][3], bh0,bh1);
                    mma_tf32(acc[mt][jj], ah[mt][0],ah[mt][1],ah[mt][2],ah[mt][3], bl0,bl1);
                }
            }
        }
    }
    __syncthreads();

    {   // epilogue GEMM3 -> plain values in sAh (stride 132); stage W4 hi/lo
        #pragma unroll
        for (int mt = 0; mt < 2; mt++){
            int rA = mt*16 + g, rB = rA + 8;
            #pragma unroll
            for (int jj = 0; jj < 2; jj++){
                int c = wid*16 + jj*8 + 2*t4;
                sAh[rA*132 + c]     = leaky(acc[mt][jj][0] + sB3[c]);
                sAh[rA*132 + c + 1] = leaky(acc[mt][jj][1] + sB3[c+1]);
                sAh[rB*132 + c]     = leaky(acc[mt][jj][2] + sB3[c]);
                sAh[rB*132 + c + 1] = leaky(acc[mt][jj][3] + sB3[c+1]);
            }
        }
        const float4* wh = (const float4*)g_W4h;
        const float4* wl = (const float4*)g_W4l;
        #pragma unroll
        for (int e = 0; e < 16; e++){
            int i4 = t + 256*e;
            int k = i4 >> 5, c4 = i4 & 31;
            *(float4*)&sWh[k*136 + 4*c4] = wh[i4];
            *(float4*)&sWl[k*136 + 4*c4] = wl[i4];
        }
    }
    __syncthreads();

    if (t < 32){   // LN1 stats
        float sum = 0.f, ss = 0.f;
        #pragma unroll 8
        for (int j = 0; j < 128; j++){ float v = sAh[t*132 + j]; sum += v; ss += v*v; }
        float mu = sum * (1.f/128.f);
        float var = ss * (1.f/128.f) - mu*mu;
        sMu[t] = mu; sIs[t] = rsqrtf(var + EPS);
    }
    __syncthreads();
    {   // LN1 apply + tf32 split in place (each element owned by one thread)
        #pragma unroll
        for (int e = 0; e < 16; e++){
            int idx = t + 256*e;
            int r = idx >> 7, c = idx & 127;
            float v = (sAh[r*132 + c] - sMu[r]) * sIs[r] * sG3[c] + sBe3[c];
            float h = tf32_rn(v);
            sAh[r*132 + c] = h;
            sAl[r*132 + c] = tf32_rn(v - h);
        }
    }
    __syncthreads();

    // ---- GEMM4: [32,128] @ [128,128] ----
    float acc2[2][2][4];
    #pragma unroll
    for (int mt = 0; mt < 2; mt++)
        #pragma unroll
        for (int jj = 0; jj < 2; jj++){
            acc2[mt][jj][0]=0.f; acc2[mt][jj][1]=0.f; acc2[mt][jj][2]=0.f; acc2[mt][jj][3]=0.f;
        }
    #pragma unroll 2
    for (int ks = 0; ks < 16; ks++){
        int k0 = ks * 8;
        float ah[2][4], al[2][4];
        #pragma unroll
        for (int mt = 0; mt < 2; mt++){
            int ro = (mt*16 + g)*132 + k0;
            ah[mt][0]=sAh[ro+t4];         al[mt][0]=sAl[ro+t4];
            ah[mt][1]=sAh[ro+8*132+t4];   al[mt][1]=sAl[ro+8*132+t4];
            ah[mt][2]=sAh[ro+t4+4];       al[mt][2]=sAl[ro+t4+4];
            ah[mt][3]=sAh[ro+8*132+t4+4]; al[mt][3]=sAl[ro+8*132+t4+4];
        }
        #pragma unroll
        for (int jj = 0; jj < 2; jj++){
            int kr = (k0 + t4)*136 + wid*16 + jj*8 + g;
            float bh0 = sWh[kr],         bl0 = sWl[kr];
            float bh1 = sWh[kr + 4*136], bl1 = sWl[kr + 4*136];
            #pragma unroll
            for (int mt = 0; mt < 2; mt++){
                mma_tf32(acc2[mt][jj], ah[mt][0],ah[mt][1],ah[mt][2],ah[mt][3], bh0,bh1);
                mma_tf32(acc2[mt][jj], al[mt][0],al[mt][1],al[mt][2],al[mt][3], bh0,bh1);
                mma_tf32(acc2[mt][jj], ah[mt][0],ah[mt][1],ah[mt][2],ah[mt][3], bl0,bl1);
            }
        }
    }
    __syncthreads();   // all sWh (W4) reads done

    float* sO2 = sWh;  // reuse (stride 132)
    #pragma unroll
    for (int mt = 0; mt < 2; mt++){
        int rA = mt*16 + g, rB = rA + 8;
        #pragma unroll
        for (int jj = 0; jj < 2; jj++){
            int c = wid*16 + jj*8 + 2*t4;
            sO2[rA*132 + c]     = leaky(acc2[mt][jj][0] + sB4[c]);
            sO2[rA*132 + c + 1] = leaky(acc2[mt][jj][1] + sB4[c+1]);
            sO2[rB*132 + c]     = leaky(acc2[mt][jj][2] + sB4[c]);
            sO2[rB*132 + c + 1] = leaky(acc2[mt][jj][3] + sB4[c+1]);
        }
    }
    __syncthreads();

    if (t < 32){   // LN2 stats
        float sum = 0.f, ss = 0.f;
        #pragma unroll 8
        for (int j = 0; j < 128; j++){ float v = sO2[t*132 + j]; sum += v; ss += v*v; }
        float mu = sum * (1.f/128.f);
        float var = ss * (1.f/128.f) - mu*mu;
        sMu[t] = mu; sIs[t] = rsqrtf(var + EPS);
    }
    __syncthreads();
    #pragma unroll
    for (int e = 0; e < 16; e++){
        int idx = t + 256*e;
        int r = idx >> 7, c = idx & 127;
        out[(g0 + r)*128 + c] = (sO2[r*132 + c] - sMu[r]) * sIs[r] * sG4[c] + sBe4[c];
    }
}

// ---------------- host ----------------
extern "C" void kernel_launch(void* const* d_in, const int* in_sizes, int n_in,
                              void* d_out, int out_size)
{
    const float* feat = (const float*)d_in[0];
    const int*   batch = (const int*)d_in[1];
    const float* W1 = (const float*)d_in[2];
    const float* b1 = (const float*)d_in[3];
    const float* g1 = (const float*)d_in[4];
    const float* be1= (const float*)d_in[5];
    const float* W2 = (const float*)d_in[6];
    const float* b2 = (const float*)d_in[7];
    const float* W3 = (const float*)d_in[8];
    const float* b3 = (const float*)d_in[9];
    const float* g3 = (const float*)d_in[10];
    const float* be3= (const float*)d_in[11];
    const float* W4 = (const float*)d_in[12];
    const float* b4 = (const float*)d_in[13];
    const float* g4 = (const float*)d_in[14];
    const float* be4= (const float*)d_in[15];

    int nrows = in_sizes[0] / 128;

    const int att_smem = ATT_SMEM_FLOATS * (int)sizeof(float);   // 110,880 B -> 2 blocks/SM
    const int fin_smem = FIN_SMEM_FLOATS * (int)sizeof(float);   // 179,712 B -> 1 block/SM
    cudaFuncSetAttribute(att_kernel,   cudaFuncAttributeMaxDynamicSharedMemorySize, att_smem);
    cudaFuncSetAttribute(final_kernel, cudaFuncAttributeMaxDynamicSharedMemorySize, fin_smem);

    detect_kernel<<<1, 1>>>(batch, nrows);
    prep_kernel<<<576, 256>>>(W3, W4);
    att_kernel<<<nrows / 64, 128, att_smem>>>(feat, W1, b1, g1, be1, W2, b2);
    aggregate_kernel<<<NGRAPH, 256>>>(feat, batch, nrows);
    final_kernel<<<NGRAPH / 32, 256, fin_smem>>>(b3, g3, be3, b4, g4, be4, (float*)d_out);
}

// round 7
// speedup vs baseline: 1.0080x; 1.0080x over previous
#include <cuda_runtime.h>
#include <cstdint>

#define NGRAPH 4096
#define EPS 1e-6f

// ---------------- device scratch (no allocations allowed) ----------------
__device__ __align__(16) float g_att[262144 * 8];          // exp attention, unnormalized [N,8]
__device__ __align__(16) float g_outflat[NGRAPH * 1024];   // aggregated [B, H*D]
__device__ __align__(16) float g_W3h[1024 * 128];
__device__ __align__(16) float g_W3l[1024 * 128];
__device__ __align__(16) float g_W4h[128 * 128];
__device__ __align__(16) float g_W4l[128 * 128];
__device__ int g_is64;                                     // batch dtype flag

__device__ __forceinline__ float leaky(float x){ return x > 0.f ? x : 0.01f * x; }

__device__ __forceinline__ float tf32_rn(float x){
    uint32_t u;
    asm("cvt.rna.tf32.f32 %0, %1;" : "=r"(u) : "f"(x));
    return __uint_as_float(u);
}

// D += A(16x8 tf32) * B(8x8 tf32), fp32 accumulate
__device__ __forceinline__ void mma_tf32(float* c,
    float a0, float a1, float a2, float a3, float b0, float b1){
    asm volatile(
      "mma.sync.aligned.m16n8k8.row.col.f32.tf32.tf32.f32 "
      "{%0,%1,%2,%3}, {%4,%5,%6,%7}, {%8,%9}, {%0,%1,%2,%3};\n"
      : "+f"(c[0]), "+f"(c[1]), "+f"(c[2]), "+f"(c[3])
      : "r"(__float_as_uint(a0)), "r"(__float_as_uint(a1)),
        "r"(__float_as_uint(a2)), "r"(__float_as_uint(a3)),
        "r"(__float_as_uint(b0)), "r"(__float_as_uint(b1)));
}

// Parallel batch dtype detection (int32 loads only; one load pair per thread).
__global__ void detect_kernel(const int* __restrict__ batch, int n){
    __shared__ int bad;
    if (threadIdx.x == 0) bad = 0;
    __syncthreads();
    int base = n / 2;                       // middle under int32 view
    int i = threadIdx.x;
    int lo = batch[base + 2*i];
    int hi = batch[base + 2*i + 1];
    if (hi != 0 || lo < 0 || lo >= NGRAPH) bad = 1;
    __syncthreads();
    if (threadIdx.x == 0) g_is64 = (bad == 0);
}

__device__ __forceinline__ int bat(const int* b, int i, int is64){
    return is64 ? b[2*i] : b[i];
}

__device__ __forceinline__ int lbound(const int* b, int n, int val, int is64){
    int lo = 0, hi = n;
    while (lo < hi){
        int mid = (lo + hi) >> 1;
        if (bat(b, mid, is64) < val) lo = mid + 1; else hi = mid;
    }
    return lo;
}

// ---------------- weight prep: one-time tf32 hi/lo split of W3, W4 ----------------
__global__ void prep_kernel(const float* __restrict__ W3, const float* __restrict__ W4){
    int i = blockIdx.x * 256 + threadIdx.x;
    if (i < 1024*128){
        float w = W3[i];
        float h = tf32_rn(w);
        g_W3h[i] = h; g_W3l[i] = tf32_rn(w - h);
    }
    int j = i - 1024*128;
    if (j >= 0 && j < 128*128){
        float w = W4[j];
        float h = tf32_rn(w);
        g_W4h[j] = h; g_W4l[j] = tf32_rn(w - h);
    }
}

// ---------------- Pass A: fused GEMM1(tf32 mma) + leaky + LN + GEMM2 + exp ----------------
// 128 rows / block, 256 threads (8 warps, one 16-row M-tile each), 2048 blocks.
#define AS 132              // sA row stride: bank = 4g+t4, conflict-free
#define WS 68               // sW1 row stride: bank = 4t4+g, conflict-free
#define ATT_SMEM_FLOATS (16896 + 8704 + 512 + 64*3 + 8 + 256)

__global__ __launch_bounds__(256) void att_kernel(
    const float* __restrict__ feat,
    const float* __restrict__ W1, const float* __restrict__ b1,
    const float* __restrict__ g1, const float* __restrict__ be1,
    const float* __restrict__ W2, const float* __restrict__ b2)
{
    extern __shared__ float sm[];
    float* sA  = sm;                 // 128 x 132 = 16896 (aliased later as sH stride 65)
    float* sW1 = sA  + 16896;        // 128 x 68  = 8704
    float* sW2 = sW1 + 8704;         // 512
    float* sB1 = sW2 + 512;          // 64
    float* sG1 = sB1 + 64;           // 64
    float* sBe1= sG1 + 64;           // 64
    float* sB2 = sBe1+ 64;           // 8
    float* sMu = sB2 + 8;            // 128
    float* sIs = sMu + 128;          // 128
    float* sH  = sA;                 // alias, stride 65 (8320 <= 16896)

    int t = threadIdx.x;
    int row0 = blockIdx.x * 128;
    int wid = t >> 5, lane = t & 31;
    int g = lane >> 2, t4 = lane & 3;

    {   // feat tile 128x128 -> sA stride 132
        const float4* gsrc = (const float4*)(feat + (size_t)row0 * 128);
        #pragma unroll
        for (int e = 0; e < 16; e++){
            int idx4 = t + 256*e;
            int r = idx4 >> 5, c4 = idx4 & 31;
            *(float4*)&sA[r*AS + 4*c4] = gsrc[idx4];
        }
    }
    {   // W1 128x64 -> sW1 stride 68
        const float4* gsrc = (const float4*)W1;
        #pragma unroll
        for (int e = 0; e < 8; e++){
            int idx4 = t + 256*e;
            int k = idx4 >> 4, c4 = idx4 & 15;
            *(float4*)&sW1[k*WS + 4*c4] = gsrc[idx4];
        }
    }
    if (t < 128) ((float4*)sW2)[t] = ((const float4*)W2)[t];
    if (t < 64){ sB1[t] = b1[t]; sG1[t] = g1[t]; sBe1[t] = be1[t]; }
    if (t < 8)  sB2[t] = b2[t];
    __syncthreads();

    // GEMM1 via tf32 split mma: each warp = 16 rows x 64 cols
    int rbase = wid * 16;
    float acc[8][4];
    #pragma unroll
    for (int j = 0; j < 8; j++){ acc[j][0]=acc[j][1]=acc[j][2]=acc[j][3]=0.f; }

    const float* A0 = sA + (rbase + g) * AS;
    const float* A1 = A0 + 8 * AS;

    #pragma unroll 4
    for (int ks = 0; ks < 16; ks++){
        int k0 = ks * 8;
        float a0 = A0[k0+t4],   a1 = A1[k0+t4];
        float a2 = A0[k0+t4+4], a3 = A1[k0+t4+4];
        float ah0=tf32_rn(a0), ah1=tf32_rn(a1), ah2=tf32_rn(a2), ah3=tf32_rn(a3);
        float al0=tf32_rn(a0-ah0), al1=tf32_rn(a1-ah1), al2=tf32_rn(a2-ah2), al3=tf32_rn(a3-ah3);
        const float* Bk = sW1 + (k0 + t4) * WS + g;
        #pragma unroll
        for (int j = 0; j < 8; j++){
            float b0 = Bk[j*8];
            float b1 = Bk[4*WS + j*8];
            float bh0 = tf32_rn(b0), bh1 = tf32_rn(b1);
            float bl0 = tf32_rn(b0-bh0), bl1 = tf32_rn(b1-bh1);
            mma_tf32(acc[j], ah0,ah1,ah2,ah3, bh0,bh1);
            mma_tf32(acc[j], al0,al1,al2,al3, bh0,bh1);
            mma_tf32(acc[j], ah0,ah1,ah2,ah3, bl0,bl1);
        }
    }
    __syncthreads();   // all sA reads complete before aliasing as sH

    {   // epilogue: bias + leaky -> sH (stride 65)
        int rA = rbase + g, rB = rA + 8;
        #pragma unroll
        for (int j = 0; j < 8; j++){
            int c = j*8 + 2*t4;
            sH[rA*65 + c]     = leaky(acc[j][0] + sB1[c]);
            sH[rA*65 + c + 1] = leaky(acc[j][1] + sB1[c+1]);
            sH[rB*65 + c]     = leaky(acc[j][2] + sB1[c]);
            sH[rB*65 + c + 1] = leaky(acc[j][3] + sB1[c+1]);
        }
    }
    __syncthreads();

    if (t < 128){   // LN stats per row
        float sum = 0.f, ss = 0.f;
        #pragma unroll 8
        for (int j = 0; j < 64; j++){ float v = sH[t*65 + j]; sum += v; ss += v*v; }
        float mu = sum * (1.f/64.f);
        float var = ss * (1.f/64.f) - mu*mu;
        sMu[t] = mu; sIs[t] = rsqrtf(var + EPS);
    }
    __syncthreads();

    {   // GEMM2 (64->8) + exp, 2 threads per row x 4 outputs
        int row = t >> 1, half = t & 1, kb = half * 4;
        float mu = sMu[row], is = sIs[row];
        float a0=0.f, a1=0.f, a2=0.f, a3=0.f;
        #pragma unroll 4
        for (int j = 0; j < 64; j++){
            float hn = (sH[row*65 + j] - mu) * is * sG1[j] + sBe1[j];
            a0 += hn * sW2[j*8 + kb + 0];
            a1 += hn * sW2[j*8 + kb + 1];
            a2 += hn * sW2[j*8 + kb + 2];
            a3 += hn * sW2[j*8 + kb + 3];
        }
        int grow = row0 + row;
        float4 o;
        o.x = __expf(a0 + sB2[kb+0]);
        o.y = __expf(a1 + sB2[kb+1]);
        o.z = __expf(a2 + sB2[kb+2]);
        o.w = __expf(a3 + sB2[kb+3]);
        *(float4*)&g_att[grow*8 + kb] = o;
    }
}

// ---------------- Pass B: warp-per-graph streaming softmax + aggregation ----------------
// 4096 warps = 512 blocks x 256 threads. No smem, no syncs: each warp streams
// its graph's contiguous row range; lane owns columns [4*lane, 4*lane+4).
__global__ __launch_bounds__(256) void aggregate_kernel(
    const float* __restrict__ feat, const int* __restrict__ batchp, int nrows)
{
    int w = (blockIdx.x * 256 + threadIdx.x) >> 5;   // graph id
    int lane = threadIdx.x & 31;
    int is64 = g_is64;
    int lo = lbound(batchp, nrows, w, is64);         // uniform within warp
    int hi = lbound(batchp, nrows, w + 1, is64);

    float4 acc[8];
    #pragma unroll
    for (int h = 0; h < 8; h++) acc[h] = make_float4(0.f, 0.f, 0.f, 0.f);
    float4 s0 = make_float4(0.f,0.f,0.f,0.f), s1 = make_float4(0.f,0.f,0.f,0.f);

    const float4* feat4 = (const float4*)feat;
    for (int r = lo; r < hi; r++){
        float4 f  = feat4[(size_t)r * 32 + lane];
        float4 a0 = *(const float4*)&g_att[(size_t)r * 8];      // uniform -> broadcast
        float4 a1 = *(const float4*)&g_att[(size_t)r * 8 + 4];
        s0.x += a0.x; s0.y += a0.y; s0.z += a0.z; s0.w += a0.w;
        s1.x += a1.x; s1.y += a1.y; s1.z += a1.z; s1.w += a1.w;
        acc[0].x += a0.x*f.x; acc[0].y += a0.x*f.y; acc[0].z += a0.x*f.z; acc[0].w += a0.x*f.w;
        acc[1].x += a0.y*f.x; acc[1].y += a0.y*f.y; acc[1].z += a0.y*f.z; acc[1].w += a0.y*f.w;
        acc[2].x += a0.z*f.x; acc[2].y += a0.z*f.y; acc[2].z += a0.z*f.z; acc[2].w += a0.z*f.w;
        acc[3].x += a0.w*f.x; acc[3].y += a0.w*f.y; acc[3].z += a0.w*f.z; acc[3].w += a0.w*f.w;
        acc[4].x += a1.x*f.x; acc[4].y += a1.x*f.y; acc[4].z += a1.x*f.z; acc[4].w += a1.x*f.w;
        acc[5].x += a1.y*f.x; acc[5].y += a1.y*f.y; acc[5].z += a1.y*f.z; acc[5].w += a1.y*f.w;
        acc[6].x += a1.z*f.x; acc[6].y += a1.z*f.y; acc[6].z += a1.z*f.z; acc[6].w += a1.z*f.w;
        acc[7].x += a1.w*f.x; acc[7].y += a1.w*f.y; acc[7].z += a1.w*f.z; acc[7].w += a1.w*f.w;
    }

    float inv[8];
    inv[0] = (hi > lo) ? 1.f / s0.x : 0.f;
    inv[1] = (hi > lo) ? 1.f / s0.y : 0.f;
    inv[2] = (hi > lo) ? 1.f / s0.z : 0.f;
    inv[3] = (hi > lo) ? 1.f / s0.w : 0.f;
    inv[4] = (hi > lo) ? 1.f / s1.x : 0.f;
    inv[5] = (hi > lo) ? 1.f / s1.y : 0.f;
    inv[6] = (hi > lo) ? 1.f / s1.z : 0.f;
    inv[7] = (hi > lo) ? 1.f / s1.w : 0.f;

    #pragma unroll
    for (int h = 0; h < 8; h++){
        float4 o;
        o.x = acc[h].x * inv[h]; o.y = acc[h].y * inv[h];
        o.z = acc[h].z * inv[h]; o.w = acc[h].w * inv[h];
        *(float4*)&g_outflat[(size_t)w*1024 + h*128 + lane*4] = o;
    }
}

// ---------------- Pass C: GEMM3(tf32)+leaky+LN, GEMM4(tf32)+leaky+LN ----------------
// 32 graphs / block, 128 blocks, 256 threads. W staged in 64-row k-tiles so
// smem = 106.7 KB -> 2 CTAs/SM. Strides: A 132 (bank 4g+t4), W 136 (bank 8t4+g).
#define FIN_SMEM_FLOATS (4224 + 4224 + 8704 + 8704 + 128*6 + 64)

__global__ __launch_bounds__(256) void final_kernel(
    const float* __restrict__ b3,
    const float* __restrict__ g3, const float* __restrict__ be3,
    const float* __restrict__ b4,
    const float* __restrict__ g4, const float* __restrict__ be4,
    float* __restrict__ out)
{
    extern __shared__ float sm[];
    float* sAh = sm;               // 32 x 132 = 4224
    float* sAl = sAh + 4224;       // 4224
    float* sWh = sAl + 4224;       // 64 x 136 = 8704
    float* sWl = sWh + 8704;       // 8704
    float* sB3 = sWl + 8704;
    float* sG3 = sB3 + 128;
    float* sBe3= sG3 + 128;
    float* sB4 = sBe3+ 128;
    float* sG4 = sB4 + 128;
    float* sBe4= sG4 + 128;
    float* sMu = sBe4+ 128;        // 32
    float* sIs = sMu + 32;         // 32

    int t = threadIdx.x;
    int g0 = blockIdx.x * 32;
    int wid = t >> 5, lane = t & 31;
    int g = lane >> 2, t4 = lane & 3;

    if (t < 128){
        sB3[t]=b3[t]; sG3[t]=g3[t]; sBe3[t]=be3[t];
        sB4[t]=b4[t]; sG4[t]=g4[t]; sBe4[t]=be4[t];
    }

    // ---- GEMM3: [32,1024] @ [1024,128] in 16 k-tiles of 64 ----
    float acc[2][2][4];
    #pragma unroll
    for (int mt = 0; mt < 2; mt++)
        #pragma unroll
        for (int jj = 0; jj < 2; jj++){
            acc[mt][jj][0]=0.f; acc[mt][jj][1]=0.f; acc[mt][jj][2]=0.f; acc[mt][jj][3]=0.f;
        }

    for (int kt = 0; kt < 16; kt++){
        __syncthreads();
        {   // stage A slice 32x64 hi/lo (512 float4, 2/thread)
            #pragma unroll
            for (int e = 0; e < 2; e++){
                int i4 = t + 256*e;
                int r = i4 >> 4, c4 = i4 & 15;
                float4 a = *(const float4*)&g_outflat[(size_t)(g0 + r)*1024 + kt*64 + 4*c4];
                float4 h, l;
                h.x = tf32_rn(a.x); l.x = tf32_rn(a.x - h.x);
                h.y = tf32_rn(a.y); l.y = tf32_rn(a.y - h.y);
                h.z = tf32_rn(a.z); l.z = tf32_rn(a.z - h.z);
                h.w = tf32_rn(a.w); l.w = tf32_rn(a.w - h.w);
                *(float4*)&sAh[r*132 + 4*c4] = h;
                *(float4*)&sAl[r*132 + 4*c4] = l;
            }
        }
        {   // stage W3 hi/lo k-tile 64x128 (pre-split in global; 2048 float4 each)
            const float4* wh = (const float4*)(g_W3h + (size_t)kt * 64 * 128);
            const float4* wl = (const float4*)(g_W3l + (size_t)kt * 64 * 128);
            #pragma unroll
            for (int e = 0; e < 8; e++){
                int i4 = t + 256*e;
                int k = i4 >> 5, c4 = i4 & 31;
                *(float4*)&sWh[k*136 + 4*c4] = wh[i4];
                *(float4*)&sWl[k*136 + 4*c4] = wl[i4];
            }
        }
        __syncthreads();

        #pragma unroll
        for (int ks = 0; ks < 8; ks++){
            int k0 = ks * 8;
            float ah[2][4], al[2][4];
            #pragma unroll
            for (int mt = 0; mt < 2; mt++){
                int ro = (mt*16 + g)*132 + k0;
                ah[mt][0]=sAh[ro+t4];         al[mt][0]=sAl[ro+t4];
                ah[mt][1]=sAh[ro+8*132+t4];   al[mt][1]=sAl[ro+8*132+t4];
                ah[mt][2]=sAh[ro+t4+4];       al[mt][2]=sAl[ro+t4+4];
                ah[mt][3]=sAh[ro+8*132+t4+4]; al[mt][3]=sAl[ro+8*132+t4+4];
            }
            #pragma unroll
            for (int jj = 0; jj < 2; jj++){
                int kr = (k0 + t4)*136 + wid*16 + jj*8 + g;
                float bh0 = sWh[kr],         bl0 = sWl[kr];
                float bh1 = sWh[kr + 4*136], bl1 = sWl[kr + 4*136];
                #pragma unroll
                for (int mt = 0; mt < 2; mt++){
                    mma_tf32(acc[mt][jj], ah[mt][0],ah[mt][1],ah[mt][2],ah[mt][3], bh0,bh1);
                    mma_tf32(acc[mt][jj], al[mt][0],al[mt][1],al[mt][2],al[mt][3], bh0,bh1);
                    mma_tf32(acc[mt][jj], ah[mt][0],ah[mt][1],ah[mt][2],ah[mt][3], bl0,bl1);
                }
            }
        }
    }
    __syncthreads();

    {   // epilogue GEMM3 -> plain values in sAh full width (stride 132)
        #pragma unroll
        for (int mt = 0; mt < 2; mt++){
            int rA = mt*16 + g, rB = rA + 8;
            #pragma unroll
            for (int jj = 0; jj < 2; jj++){
                int c = wid*16 + jj*8 + 2*t4;
                sAh[rA*132 + c]     = leaky(acc[mt][jj][0] + sB3[c]);
                sAh[rA*132 + c + 1] = leaky(acc[mt][jj][1] + sB3[c+1]);
                sAh[rB*132 + c]     = leaky(acc[mt][jj][2] + sB3[c]);
                sAh[rB*132 + c + 1] = leaky(acc[mt][jj][3] + sB3[c+1]);
            }
        }
    }
    __syncthreads();

    if (t < 32){   // LN1 stats
        float sum = 0.f, ss = 0.f;
        #pragma unroll 8
        for (int j = 0; j < 128; j++){ float v = sAh[t*132 + j]; sum += v; ss += v*v; }
        float mu = sum * (1.f/128.f);
        float var = ss * (1.f/128.f) - mu*mu;
        sMu[t] = mu; sIs[t] = rsqrtf(var + EPS);
    }
    __syncthreads();
    {   // LN1 apply + tf32 split in place
        #pragma unroll
        for (int e = 0; e < 16; e++){
            int idx = t + 256*e;
            int r = idx >> 7, c = idx & 127;
            float v = (sAh[r*132 + c] - sMu[r]) * sIs[r] * sG3[c] + sBe3[c];
            float h = tf32_rn(v);
            sAh[r*132 + c] = h;
            sAl[r*132 + c] = tf32_rn(v - h);
        }
    }

    // ---- GEMM4: [32,128] @ [128,128] in 2 half-K tiles of 64 ----
    float acc2[2][2][4];
    #pragma unroll
    for (int mt = 0; mt < 2; mt++)
        #pragma unroll
        for (int jj = 0; jj < 2; jj++){
            acc2[mt][jj][0]=0.f; acc2[mt][jj][1]=0.f; acc2[mt][jj][2]=0.f; acc2[mt][jj][3]=0.f;
        }

    for (int half = 0; half < 2; half++){
        __syncthreads();
        {   // stage W4 rows [half*64, half*64+64) hi/lo
            const float4* wh = (const float4*)(g_W4h + (size_t)half * 64 * 128);
            const float4* wl = (const float4*)(g_W4l + (size_t)half * 64 * 128);
            #pragma unroll
            for (int e = 0; e < 8; e++){
                int i4 = t + 256*e;
                int k = i4 >> 5, c4 = i4 & 31;
                *(float4*)&sWh[k*136 + 4*c4] = wh[i4];
                *(float4*)&sWl[k*136 + 4*c4] = wl[i4];
            }
        }
        __syncthreads();

        #pragma unroll
        for (int ks = 0; ks < 8; ks++){
            int k0 = half*64 + ks*8;           // A column
            int kw = ks*8;                     // W smem row
            float ah[2][4], al[2][4];
            #pragma unroll
            for (int mt = 0; mt < 2; mt++){
                int ro = (mt*16 + g)*132 + k0;
                ah[mt][0]=sAh[ro+t4];         al[mt][0]=sAl[ro+t4];
                ah[mt][1]=sAh[ro+8*132+t4];   al[mt][1]=sAl[ro+8*132+t4];
                ah[mt][2]=sAh[ro+t4+4];       al[mt][2]=sAl[ro+t4+4];
                ah[mt][3]=sAh[ro+8*132+t4+4]; al[mt][3]=sAl[ro+8*132+t4+4];
            }
            #pragma unroll
            for (int jj = 0; jj < 2; jj++){
                int kr = (kw + t4)*136 + wid*16 + jj*8 + g;
                float bh0 = sWh[kr],         bl0 = sWl[kr];
                float bh1 = sWh[kr + 4*136], bl1 = sWl[kr + 4*136];
                #pragma unroll
                for (int mt = 0; mt < 2; mt++){
                    mma_tf32(acc2[mt][jj], ah[mt][0],ah[mt][1],ah[mt][2],ah[mt][3], bh0,bh1);
                    mma_tf32(acc2[mt][jj], al[mt][0],al[mt][1],al[mt][2],al[mt][3], bh0,bh1);
                    mma_tf32(acc2[mt][jj], ah[mt][0],ah[mt][1],ah[mt][2],ah[mt][3], bl0,bl1);
                }
            }
        }
    }
    __syncthreads();   // all sWh/sWl reads done

    float* sO2 = sWh;  // reuse for output tile (stride 132; 4224 <= 8704)
    #pragma unroll
    for (int mt = 0; mt < 2; mt++){
        int rA = mt*16 + g, rB = rA + 8;
        #pragma unroll
        for (int jj = 0; jj < 2; jj++){
            int c = wid*16 + jj*8 + 2*t4;
            sO2[rA*132 + c]     = leaky(acc2[mt][jj][0] + sB4[c]);
            sO2[rA*132 + c + 1] = leaky(acc2[mt][jj][1] + sB4[c+1]);
            sO2[rB*132 + c]     = leaky(acc2[mt][jj][2] + sB4[c]);
            sO2[rB*132 + c + 1] = leaky(acc2[mt][jj][3] + sB4[c+1]);
        }
    }
    __syncthreads();

    if (t < 32){   // LN2 stats
        float sum = 0.f, ss = 0.f;
        #pragma unroll 8
        for (int j = 0; j < 128; j++){ float v = sO2[t*132 + j]; sum += v; ss += v*v; }
        float mu = sum * (1.f/128.f);
        float var = ss * (1.f/128.f) - mu*mu;
        sMu[t] = mu; sIs[t] = rsqrtf(var + EPS);
    }
    __syncthreads();
    #pragma unroll
    for (int e = 0; e < 16; e++){
        int idx = t + 256*e;
        int r = idx >> 7, c = idx & 127;
        out[(g0 + r)*128 + c] = (sO2[r*132 + c] - sMu[r]) * sIs[r] * sG4[c] + sBe4[c];
    }
}

// ---------------- host ----------------
extern "C" void kernel_launch(void* const* d_in, const int* in_sizes, int n_in,
                              void* d_out, int out_size)
{
    const float* feat = (const float*)d_in[0];
    const int*   batch = (const int*)d_in[1];
    const float* W1 = (const float*)d_in[2];
    const float* b1 = (const float*)d_in[3];
    const float* g1 = (const float*)d_in[4];
    const float* be1= (const float*)d_in[5];
    const float* W2 = (const float*)d_in[6];
    const float* b2 = (const float*)d_in[7];
    const float* W3 = (const float*)d_in[8];
    const float* b3 = (const float*)d_in[9];
    const float* g3 = (const float*)d_in[10];
    const float* be3= (const float*)d_in[11];
    const float* W4 = (const float*)d_in[12];
    const float* b4 = (const float*)d_in[13];
    const float* g4 = (const float*)d_in[14];
    const float* be4= (const float*)d_in[15];

    int nrows = in_sizes[0] / 128;

    const int att_smem = ATT_SMEM_FLOATS * (int)sizeof(float);   // 106,272 B -> 2 CTAs/SM
    const int fin_smem = FIN_SMEM_FLOATS * (int)sizeof(float);   // 106,752 B -> 2 CTAs/SM
    cudaFuncSetAttribute(att_kernel,   cudaFuncAttributeMaxDynamicSharedMemorySize, att_smem);
    cudaFuncSetAttribute(final_kernel, cudaFuncAttributeMaxDynamicSharedMemorySize, fin_smem);

    detect_kernel<<<1, 256>>>(batch, nrows);
    prep_kernel<<<576, 256>>>(W3, W4);
    att_kernel<<<nrows / 128, 256, att_smem>>>(feat, W1, b1, g1, be1, W2, b2);
    aggregate_kernel<<<NGRAPH / 8, 256>>>(feat, batch, nrows);
    final_kernel<<<NGRAPH / 32, 256, fin_smem>>>(b3, g3, be3, b4, g4, be4, (float*)d_out);
}